// round 4
// baseline (speedup 1.0000x reference)
#include <cuda_runtime.h>

#define NSTATE (1u << 22)

// XOR swizzle on float4-unit index: permutes within 128B rows only,
// preserves 16B alignment, spreads bank columns for strided patterns.
__device__ __forceinline__ int SW(int u) {
    return u ^ ((u >> 3) & 7) ^ ((u >> 6) & 7);
}

// one 2x2 rotation butterfly: new = (c*I - i*s*X) * old
__device__ __forceinline__ void gate1(float& r0, float& i0, float& r1, float& i1,
                                      float c, float s)
{
    float nr0 = c * r0 + s * i1;
    float ni0 = c * i0 - s * r1;
    float nr1 = c * r1 + s * i0;
    float ni1 = c * i1 - s * r0;
    r0 = nr0; i0 = ni0; r1 = nr1; i1 = ni1;
}

// gate on a pair of interleaved units (each unit = 2 complex: r0,i0,r1,i1)
__device__ __forceinline__ void gateU(float4& A, float4& B, float c, float s)
{
    gate1(A.x, A.y, B.x, B.y, c, s);
    gate1(A.z, A.w, B.z, B.w, c, s);
}

// gate across two (R,I) float4 pairs, componentwise (4 complex each side)
__device__ __forceinline__ void gateV(float4& Ra, float4& Ia, float4& Rb, float4& Ib,
                                      float c, float s)
{
    gate1(Ra.x, Ia.x, Rb.x, Ib.x, c, s);
    gate1(Ra.y, Ia.y, Rb.y, Ib.y, c, s);
    gate1(Ra.z, Ia.z, Rb.z, Ib.z, c, s);
    gate1(Ra.w, Ia.w, Rb.w, Ib.w, c, s);
}

__device__ __forceinline__ void getcs(const float* __restrict__ ang, int i,
                                      float& c, float& s)
{
    sincosf(0.5f * __ldg(ang + i), &s, &c);
}

// ---------------------------------------------------------------------------
// Kernel A: gates on global bits 0..11 (angle[21..10]).
// Tile = 4096 contiguous complex. 256 threads.
// R1: 16 contiguous complex/thread from global, gates bits 0-3.
// R2: bits 4-6, R3: bits 7-9, R4: bits 10-11 + vectorized global store.
// Shared layout: float4 unit u holds complex (2u, 2u+1) as (r,i,r,i).
// ---------------------------------------------------------------------------
__global__ void __launch_bounds__(256, 4) gateA(const float* __restrict__ xr,
                                                const float* __restrict__ xi,
                                                const float* __restrict__ ang,
                                                float* __restrict__ outr,
                                                float* __restrict__ outi)
{
    __shared__ float4 sm[2048];               // 32KB
    const int t = threadIdx.x;
    const unsigned base = (unsigned)blockIdx.x << 12;

    // ---- R1: load 16 contiguous complex, gate bits 0..3 in registers ----
    {
        float4 R[4], I[4];
        const float4* pr = reinterpret_cast<const float4*>(xr + base) + t * 4;
        const float4* pi = reinterpret_cast<const float4*>(xi + base) + t * 4;
#pragma unroll
        for (int q = 0; q < 4; ++q) { R[q] = pr[q]; I[q] = pi[q]; }

        float c, s;
        getcs(ang, 21, c, s);                 // bit 0: within-float4 pairs (x,y),(z,w)
#pragma unroll
        for (int q = 0; q < 4; ++q) {
            gate1(R[q].x, I[q].x, R[q].y, I[q].y, c, s);
            gate1(R[q].z, I[q].z, R[q].w, I[q].w, c, s);
        }
        getcs(ang, 20, c, s);                 // bit 1: (x,z),(y,w)
#pragma unroll
        for (int q = 0; q < 4; ++q) {
            gate1(R[q].x, I[q].x, R[q].z, I[q].z, c, s);
            gate1(R[q].y, I[q].y, R[q].w, I[q].w, c, s);
        }
        getcs(ang, 19, c, s);                 // bit 2: q pairs (0,1),(2,3)
        gateV(R[0], I[0], R[1], I[1], c, s);
        gateV(R[2], I[2], R[3], I[3], c, s);
        getcs(ang, 18, c, s);                 // bit 3: q pairs (0,2),(1,3)
        gateV(R[0], I[0], R[2], I[2], c, s);
        gateV(R[1], I[1], R[3], I[3], c, s);

#pragma unroll
        for (int m = 0; m < 8; ++m) {
            int q = m >> 1;
            float4 u = (m & 1) ? make_float4(R[q].z, I[q].z, R[q].w, I[q].w)
                               : make_float4(R[q].x, I[q].x, R[q].y, I[q].y);
            sm[SW(t * 8 + m)] = u;
        }
    }
    __syncthreads();

    float4 U[8];

    // ---- R2: gates bits 4-6 (unit bits 3-5) ----
    {
        const int lo = t & 7, hi = t >> 3;
#pragma unroll
        for (int j = 0; j < 8; ++j) U[j] = sm[SW((hi << 6) | (j << 3) | lo)];
        float c, s;
        getcs(ang, 17, c, s);
#pragma unroll
        for (int p = 0; p < 8; ++p) if (!(p & 1)) gateU(U[p], U[p | 1], c, s);
        getcs(ang, 16, c, s);
#pragma unroll
        for (int p = 0; p < 8; ++p) if (!(p & 2)) gateU(U[p], U[p | 2], c, s);
        getcs(ang, 15, c, s);
#pragma unroll
        for (int p = 0; p < 8; ++p) if (!(p & 4)) gateU(U[p], U[p | 4], c, s);
#pragma unroll
        for (int j = 0; j < 8; ++j) sm[SW((hi << 6) | (j << 3) | lo)] = U[j];
    }
    __syncthreads();

    // ---- R3: gates bits 7-9 (unit bits 6-8) ----
    {
        const int lo = t & 63, hi = t >> 6;
#pragma unroll
        for (int j = 0; j < 8; ++j) U[j] = sm[SW((hi << 9) | (j << 6) | lo)];
        float c, s;
        getcs(ang, 14, c, s);
#pragma unroll
        for (int p = 0; p < 8; ++p) if (!(p & 1)) gateU(U[p], U[p | 1], c, s);
        getcs(ang, 13, c, s);
#pragma unroll
        for (int p = 0; p < 8; ++p) if (!(p & 2)) gateU(U[p], U[p | 2], c, s);
        getcs(ang, 12, c, s);
#pragma unroll
        for (int p = 0; p < 8; ++p) if (!(p & 4)) gateU(U[p], U[p | 4], c, s);
#pragma unroll
        for (int j = 0; j < 8; ++j) sm[SW((hi << 9) | (j << 6) | lo)] = U[j];
    }
    __syncthreads();

    // ---- R4: gates bits 10-11 (unit bits 9-10), global store ----
    {
#pragma unroll
        for (int jh = 0; jh < 4; ++jh)
#pragma unroll
            for (int jl = 0; jl < 2; ++jl)
                U[jh * 2 + jl] = sm[SW((jh << 9) | (t << 1) | jl)];
        float c, s;
        getcs(ang, 11, c, s);                 // bit 10: idx stride 2
#pragma unroll
        for (int p = 0; p < 8; ++p) if (!(p & 2)) gateU(U[p], U[p | 2], c, s);
        getcs(ang, 10, c, s);                 // bit 11: idx stride 4
#pragma unroll
        for (int p = 0; p < 8; ++p) if (!(p & 4)) gateU(U[p], U[p | 4], c, s);
#pragma unroll
        for (int jh = 0; jh < 4; ++jh) {
            float4 A = U[jh * 2], B = U[jh * 2 + 1];
            unsigned g = base + ((unsigned)jh << 10) + ((unsigned)t << 2);
            *reinterpret_cast<float4*>(outr + g) = make_float4(A.x, A.z, B.x, B.z);
            *reinterpret_cast<float4*>(outi + g) = make_float4(A.y, A.w, B.y, B.w);
        }
    }
}

// ---------------------------------------------------------------------------
// Kernel B: gates on global bits 12..21 (angle[9..0]). In-place on out.
// Tile = 4 contiguous (bits 0-1) x 1024 strided h (bits 12-21) = 4096 complex.
// 256 threads. Unit u = h*2 + q (q = lo pair index).
// Rounds: fill; h0-2; h3-5; h6-8; h9 + global store.
// ---------------------------------------------------------------------------
__global__ void __launch_bounds__(256, 4) gateB(float* __restrict__ dr,
                                                float* __restrict__ di,
                                                const float* __restrict__ ang)
{
    __shared__ float4 sm[2048];               // 32KB
    const int t = threadIdx.x;
    const unsigned base = (unsigned)blockIdx.x << 2;   // k bits 2-11

    // ---- fill: 4 h per thread, 1 float4 per plane per h ----
#pragma unroll
    for (int d = 0; d < 4; ++d) {
        int h = t + 256 * d;
        unsigned g = ((unsigned)h << 12) + base;
        float4 r = *reinterpret_cast<const float4*>(dr + g);
        float4 i = *reinterpret_cast<const float4*>(di + g);
        sm[SW(h * 2)]     = make_float4(r.x, i.x, r.y, i.y);
        sm[SW(h * 2 + 1)] = make_float4(r.z, i.z, r.w, i.w);
    }
    __syncthreads();

    float4 U[8];

    // ---- Rd1: gates h0-2 (unit bits 1-3) -> angle[9,8,7] ----
    {
        const int q = t & 1, hh = t >> 1;
#pragma unroll
        for (int j = 0; j < 8; ++j) U[j] = sm[SW((hh << 4) | (j << 1) | q)];
        float c, s;
        getcs(ang, 9, c, s);
#pragma unroll
        for (int p = 0; p < 8; ++p) if (!(p & 1)) gateU(U[p], U[p | 1], c, s);
        getcs(ang, 8, c, s);
#pragma unroll
        for (int p = 0; p < 8; ++p) if (!(p & 2)) gateU(U[p], U[p | 2], c, s);
        getcs(ang, 7, c, s);
#pragma unroll
        for (int p = 0; p < 8; ++p) if (!(p & 4)) gateU(U[p], U[p | 4], c, s);
#pragma unroll
        for (int j = 0; j < 8; ++j) sm[SW((hh << 4) | (j << 1) | q)] = U[j];
    }
    __syncthreads();

    // ---- Rd2: gates h3-5 (unit bits 4-6) -> angle[6,5,4] ----
    {
        const int lo = t & 15, hi = t >> 4;
#pragma unroll
        for (int j = 0; j < 8; ++j) U[j] = sm[SW((hi << 7) | (j << 4) | lo)];
        float c, s;
        getcs(ang, 6, c, s);
#pragma unroll
        for (int p = 0; p < 8; ++p) if (!(p & 1)) gateU(U[p], U[p | 1], c, s);
        getcs(ang, 5, c, s);
#pragma unroll
        for (int p = 0; p < 8; ++p) if (!(p & 2)) gateU(U[p], U[p | 2], c, s);
        getcs(ang, 4, c, s);
#pragma unroll
        for (int p = 0; p < 8; ++p) if (!(p & 4)) gateU(U[p], U[p | 4], c, s);
#pragma unroll
        for (int j = 0; j < 8; ++j) sm[SW((hi << 7) | (j << 4) | lo)] = U[j];
    }
    __syncthreads();

    // ---- Rd3: gates h6-8 (unit bits 7-9) -> angle[3,2,1] ----
    {
        const int lo = t & 127, hi = t >> 7;
#pragma unroll
        for (int j = 0; j < 8; ++j) U[j] = sm[SW((hi << 10) | (j << 7) | lo)];
        float c, s;
        getcs(ang, 3, c, s);
#pragma unroll
        for (int p = 0; p < 8; ++p) if (!(p & 1)) gateU(U[p], U[p | 1], c, s);
        getcs(ang, 2, c, s);
#pragma unroll
        for (int p = 0; p < 8; ++p) if (!(p & 2)) gateU(U[p], U[p | 2], c, s);
        getcs(ang, 1, c, s);
#pragma unroll
        for (int p = 0; p < 8; ++p) if (!(p & 4)) gateU(U[p], U[p | 4], c, s);
#pragma unroll
        for (int j = 0; j < 8; ++j) sm[SW((hi << 10) | (j << 7) | lo)] = U[j];
    }
    __syncthreads();

    // ---- Rd4: gate h9 (unit bit 10) -> angle[0]; global store ----
    {
#pragma unroll
        for (int jh = 0; jh < 2; ++jh)
#pragma unroll
            for (int jl = 0; jl < 4; ++jl)
                U[(jh << 2) | jl] = sm[SW((jh << 10) | (t << 2) | jl)];
        float c, s;
        getcs(ang, 0, c, s);                  // h9: idx stride 4
#pragma unroll
        for (int p = 0; p < 8; ++p) if (!(p & 4)) gateU(U[p], U[p | 4], c, s);
#pragma unroll
        for (int jh = 0; jh < 2; ++jh)
#pragma unroll
            for (int p2 = 0; p2 < 2; ++p2) {
                float4 A = U[(jh << 2) | (p2 * 2)];
                float4 B = U[(jh << 2) | (p2 * 2) | 1];
                int h = (jh << 9) | (t << 1) | p2;
                unsigned g = ((unsigned)h << 12) + base;
                *reinterpret_cast<float4*>(dr + g) = make_float4(A.x, A.z, B.x, B.z);
                *reinterpret_cast<float4*>(di + g) = make_float4(A.y, A.w, B.y, B.w);
            }
    }
}

extern "C" void kernel_launch(void* const* d_in, const int* in_sizes, int n_in,
                              void* d_out, int out_size)
{
    const float* xr  = (const float*)d_in[0];
    const float* xi  = (const float*)d_in[1];
    const float* ang = (const float*)d_in[2];
    float* outr = (float*)d_out;
    float* outi = outr + NSTATE;

    // Pass 1: gates on bits 0..11 (input -> out)
    gateA<<<NSTATE / 4096, 256>>>(xr, xi, ang, outr, outi);

    // Pass 2: gates on bits 12..21 (in-place on out)
    gateB<<<NSTATE / 4096, 256>>>(outr, outi, ang);
}

// round 5
// speedup vs baseline: 1.1943x; 1.1943x over previous
#include <cuda_runtime.h>

#define NSTATE (1u << 22)

// swizzles on float4-unit indices: permute within 128B rows, keep 16B alignment
__device__ __forceinline__ int SW(int u) {          // gateA (2048 units)
    return u ^ ((u >> 3) & 7) ^ ((u >> 6) & 7);
}
__device__ __forceinline__ int SWB(int u) {         // gateB (4096 units)
    return u ^ ((u >> 4) & 7) ^ ((u >> 9) & 7);
}

// one 2x2 rotation butterfly: new = (c*I - i*s*X) * old
__device__ __forceinline__ void gate1(float& r0, float& i0, float& r1, float& i1,
                                      float c, float s)
{
    float nr0 = c * r0 + s * i1;
    float ni0 = c * i0 - s * r1;
    float nr1 = c * r1 + s * i0;
    float ni1 = c * i1 - s * r0;
    r0 = nr0; i0 = ni0; r1 = nr1; i1 = ni1;
}

// gate on a pair of interleaved units (each unit = 2 complex: r0,i0,r1,i1)
__device__ __forceinline__ void gateU(float4& A, float4& B, float c, float s)
{
    gate1(A.x, A.y, B.x, B.y, c, s);
    gate1(A.z, A.w, B.z, B.w, c, s);
}

// gate across two (R,I) float4 pairs, componentwise (4 complex each side)
__device__ __forceinline__ void gateV(float4& Ra, float4& Ia, float4& Rb, float4& Ib,
                                      float c, float s)
{
    gate1(Ra.x, Ia.x, Rb.x, Ib.x, c, s);
    gate1(Ra.y, Ia.y, Rb.y, Ib.y, c, s);
    gate1(Ra.z, Ia.z, Rb.z, Ib.z, c, s);
    gate1(Ra.w, Ia.w, Rb.w, Ib.w, c, s);
}

__device__ __forceinline__ void getcs(const float* __restrict__ ang, int i,
                                      float& c, float& s)
{
    sincosf(0.5f * __ldg(ang + i), &s, &c);
}

// ---------------------------------------------------------------------------
// Kernel A: gates on global bits 0..11 (angle[21..10]).
// Tile = 4096 contiguous complex. 256 threads.
// R1: 16 contiguous complex/thread from global, gates bits 0-3.
// R2: bits 4-6, R3: bits 7-9, R4: bits 10-11 + vectorized global store.
// ---------------------------------------------------------------------------
__global__ void __launch_bounds__(256, 4) gateA(const float* __restrict__ xr,
                                                const float* __restrict__ xi,
                                                const float* __restrict__ ang,
                                                float* __restrict__ outr,
                                                float* __restrict__ outi)
{
    __shared__ float4 sm[2048];               // 32KB
    const int t = threadIdx.x;
    const unsigned base = (unsigned)blockIdx.x << 12;

    // ---- R1: load 16 contiguous complex, gate bits 0..3 in registers ----
    {
        float4 R[4], I[4];
        const float4* pr = reinterpret_cast<const float4*>(xr + base) + t * 4;
        const float4* pi = reinterpret_cast<const float4*>(xi + base) + t * 4;
#pragma unroll
        for (int q = 0; q < 4; ++q) { R[q] = pr[q]; I[q] = pi[q]; }

        float c, s;
        getcs(ang, 21, c, s);                 // bit 0
#pragma unroll
        for (int q = 0; q < 4; ++q) {
            gate1(R[q].x, I[q].x, R[q].y, I[q].y, c, s);
            gate1(R[q].z, I[q].z, R[q].w, I[q].w, c, s);
        }
        getcs(ang, 20, c, s);                 // bit 1
#pragma unroll
        for (int q = 0; q < 4; ++q) {
            gate1(R[q].x, I[q].x, R[q].z, I[q].z, c, s);
            gate1(R[q].y, I[q].y, R[q].w, I[q].w, c, s);
        }
        getcs(ang, 19, c, s);                 // bit 2
        gateV(R[0], I[0], R[1], I[1], c, s);
        gateV(R[2], I[2], R[3], I[3], c, s);
        getcs(ang, 18, c, s);                 // bit 3
        gateV(R[0], I[0], R[2], I[2], c, s);
        gateV(R[1], I[1], R[3], I[3], c, s);

#pragma unroll
        for (int m = 0; m < 8; ++m) {
            int q = m >> 1;
            float4 u = (m & 1) ? make_float4(R[q].z, I[q].z, R[q].w, I[q].w)
                               : make_float4(R[q].x, I[q].x, R[q].y, I[q].y);
            sm[SW(t * 8 + m)] = u;
        }
    }
    __syncthreads();

    float4 U[8];

    // ---- R2: gates bits 4-6 (unit bits 3-5) ----
    {
        const int lo = t & 7, hi = t >> 3;
#pragma unroll
        for (int j = 0; j < 8; ++j) U[j] = sm[SW((hi << 6) | (j << 3) | lo)];
        float c, s;
        getcs(ang, 17, c, s);
#pragma unroll
        for (int p = 0; p < 8; ++p) if (!(p & 1)) gateU(U[p], U[p | 1], c, s);
        getcs(ang, 16, c, s);
#pragma unroll
        for (int p = 0; p < 8; ++p) if (!(p & 2)) gateU(U[p], U[p | 2], c, s);
        getcs(ang, 15, c, s);
#pragma unroll
        for (int p = 0; p < 8; ++p) if (!(p & 4)) gateU(U[p], U[p | 4], c, s);
#pragma unroll
        for (int j = 0; j < 8; ++j) sm[SW((hi << 6) | (j << 3) | lo)] = U[j];
    }
    __syncthreads();

    // ---- R3: gates bits 7-9 (unit bits 6-8) ----
    {
        const int lo = t & 63, hi = t >> 6;
#pragma unroll
        for (int j = 0; j < 8; ++j) U[j] = sm[SW((hi << 9) | (j << 6) | lo)];
        float c, s;
        getcs(ang, 14, c, s);
#pragma unroll
        for (int p = 0; p < 8; ++p) if (!(p & 1)) gateU(U[p], U[p | 1], c, s);
        getcs(ang, 13, c, s);
#pragma unroll
        for (int p = 0; p < 8; ++p) if (!(p & 2)) gateU(U[p], U[p | 2], c, s);
        getcs(ang, 12, c, s);
#pragma unroll
        for (int p = 0; p < 8; ++p) if (!(p & 4)) gateU(U[p], U[p | 4], c, s);
#pragma unroll
        for (int j = 0; j < 8; ++j) sm[SW((hi << 9) | (j << 6) | lo)] = U[j];
    }
    __syncthreads();

    // ---- R4: gates bits 10-11 (unit bits 9-10), global store ----
    {
#pragma unroll
        for (int jh = 0; jh < 4; ++jh)
#pragma unroll
            for (int jl = 0; jl < 2; ++jl)
                U[jh * 2 + jl] = sm[SW((jh << 9) | (t << 1) | jl)];
        float c, s;
        getcs(ang, 11, c, s);                 // bit 10
#pragma unroll
        for (int p = 0; p < 8; ++p) if (!(p & 2)) gateU(U[p], U[p | 2], c, s);
        getcs(ang, 10, c, s);                 // bit 11
#pragma unroll
        for (int p = 0; p < 8; ++p) if (!(p & 4)) gateU(U[p], U[p | 4], c, s);
#pragma unroll
        for (int jh = 0; jh < 4; ++jh) {
            float4 A = U[jh * 2], B = U[jh * 2 + 1];
            unsigned g = base + ((unsigned)jh << 10) + ((unsigned)t << 2);
            *reinterpret_cast<float4*>(outr + g) = make_float4(A.x, A.z, B.x, B.z);
            *reinterpret_cast<float4*>(outi + g) = make_float4(A.y, A.w, B.y, B.w);
        }
    }
}

// ---------------------------------------------------------------------------
// Kernel B: gates on global bits 12..21 (angle[9..0]). In-place on out.
// Tile = 8 contiguous (bits 0-2) x 1024 strided h (bits 12-21) = 8192 complex.
// 512 threads, 64KB dynamic smem (4096 float4 units; unit = 2 complex r,i,r,i;
// unit index u = (h<<2) | ulh, ulh = lo-pair 0..3).
// Rounds: fill+gates(h8,h9); h0-2; h3-5; h6-7 + store. 32B/h/plane global
// segments -> 100% sector efficiency.
// ---------------------------------------------------------------------------
__global__ void __launch_bounds__(512, 2) gateB(float* __restrict__ dr,
                                                float* __restrict__ di,
                                                const float* __restrict__ ang)
{
    extern __shared__ float4 sm[];            // 4096 units = 64KB
    const int t = threadIdx.x;
    const unsigned base = (unsigned)blockIdx.x << 3;   // k bits 3-11

    float4 U[8];

    // ---- fill + gates h8 (angle[1]), h9 (angle[0]) ----
    {
        const int uq = t & 1;                 // which 16B half of the 32B segment
        const int hm = t >> 1;                // h[0..7]
        float c, s;
#pragma unroll
        for (int j = 0; j < 4; ++j) {         // j = (h9<<1)|h8
            unsigned h = ((unsigned)j << 8) | (unsigned)hm;
            unsigned g = (h << 12) + base + 4u * (unsigned)uq;
            float4 R = *reinterpret_cast<const float4*>(dr + g);
            float4 I = *reinterpret_cast<const float4*>(di + g);
            U[2 * j]     = make_float4(R.x, I.x, R.y, I.y);
            U[2 * j + 1] = make_float4(R.z, I.z, R.w, I.w);
        }
        getcs(ang, 1, c, s);                  // h8: reg stride 2
#pragma unroll
        for (int p = 0; p < 8; ++p) if (!(p & 2)) gateU(U[p], U[p | 2], c, s);
        getcs(ang, 0, c, s);                  // h9: reg stride 4
#pragma unroll
        for (int p = 0; p < 8; ++p) if (!(p & 4)) gateU(U[p], U[p | 4], c, s);
#pragma unroll
        for (int j = 0; j < 4; ++j)
#pragma unroll
            for (int ulo = 0; ulo < 2; ++ulo)
                sm[SWB((j << 10) | (hm << 2) | (uq << 1) | ulo)] = U[2 * j + ulo];
    }
    __syncthreads();

    // ---- Rd1: gates h0,h1,h2 (angle[9,8,7]) ----
    {
        const int ul = t & 3, hp = t >> 2;    // hp = h[3..9]
#pragma unroll
        for (int j = 0; j < 8; ++j) U[j] = sm[SWB((hp << 5) | (j << 2) | ul)];
        float c, s;
        getcs(ang, 9, c, s);
#pragma unroll
        for (int p = 0; p < 8; ++p) if (!(p & 1)) gateU(U[p], U[p | 1], c, s);
        getcs(ang, 8, c, s);
#pragma unroll
        for (int p = 0; p < 8; ++p) if (!(p & 2)) gateU(U[p], U[p | 2], c, s);
        getcs(ang, 7, c, s);
#pragma unroll
        for (int p = 0; p < 8; ++p) if (!(p & 4)) gateU(U[p], U[p | 4], c, s);
#pragma unroll
        for (int j = 0; j < 8; ++j) sm[SWB((hp << 5) | (j << 2) | ul)] = U[j];
    }
    __syncthreads();

    // ---- Rd2: gates h3,h4,h5 (angle[6,5,4]) ----
    {
        const int ul = t & 3, hl = (t >> 2) & 7, ht = t >> 5;  // ht = h[6..9]
#pragma unroll
        for (int j = 0; j < 8; ++j)
            U[j] = sm[SWB((ht << 8) | (j << 5) | (hl << 2) | ul)];
        float c, s;
        getcs(ang, 6, c, s);
#pragma unroll
        for (int p = 0; p < 8; ++p) if (!(p & 1)) gateU(U[p], U[p | 1], c, s);
        getcs(ang, 5, c, s);
#pragma unroll
        for (int p = 0; p < 8; ++p) if (!(p & 2)) gateU(U[p], U[p | 2], c, s);
        getcs(ang, 4, c, s);
#pragma unroll
        for (int p = 0; p < 8; ++p) if (!(p & 4)) gateU(U[p], U[p | 4], c, s);
#pragma unroll
        for (int j = 0; j < 8; ++j)
            sm[SWB((ht << 8) | (j << 5) | (hl << 2) | ul)] = U[j];
    }
    __syncthreads();

    // ---- Rd3: gates h6,h7 (angle[3,2]) + coalesced global store ----
    {
        const int uq = t & 1, hm6 = (t >> 1) & 63, h89 = t >> 7;
#pragma unroll
        for (int j = 0; j < 4; ++j)           // j = h[6..7]
#pragma unroll
            for (int ulo = 0; ulo < 2; ++ulo)
                U[(j << 1) | ulo] =
                    sm[SWB((h89 << 10) | (j << 8) | (hm6 << 2) | (uq << 1) | ulo)];
        float c, s;
        getcs(ang, 3, c, s);                  // h6: reg stride 2
#pragma unroll
        for (int p = 0; p < 8; ++p) if (!(p & 2)) gateU(U[p], U[p | 2], c, s);
        getcs(ang, 2, c, s);                  // h7: reg stride 4
#pragma unroll
        for (int p = 0; p < 8; ++p) if (!(p & 4)) gateU(U[p], U[p | 4], c, s);
#pragma unroll
        for (int j = 0; j < 4; ++j) {
            float4 A = U[j << 1], B = U[(j << 1) | 1];
            unsigned h = ((unsigned)h89 << 8) | ((unsigned)j << 6) | (unsigned)hm6;
            unsigned g = (h << 12) + base + 4u * (unsigned)uq;
            *reinterpret_cast<float4*>(dr + g) = make_float4(A.x, A.z, B.x, B.z);
            *reinterpret_cast<float4*>(di + g) = make_float4(A.y, A.w, B.y, B.w);
        }
    }
}

extern "C" void kernel_launch(void* const* d_in, const int* in_sizes, int n_in,
                              void* d_out, int out_size)
{
    const float* xr  = (const float*)d_in[0];
    const float* xi  = (const float*)d_in[1];
    const float* ang = (const float*)d_in[2];
    float* outr = (float*)d_out;
    float* outi = outr + NSTATE;

    // Pass 1: gates on bits 0..11 (input -> out)
    gateA<<<NSTATE / 4096, 256>>>(xr, xi, ang, outr, outi);

    // Pass 2: gates on bits 12..21 (in-place on out)
    const int shB = 4096 * sizeof(float4);    // 64KB
    cudaFuncSetAttribute(gateB, cudaFuncAttributeMaxDynamicSharedMemorySize, shB);
    gateB<<<NSTATE / 8192, 512, shB>>>(outr, outi, ang);
}